// round 5
// baseline (speedup 1.0000x reference)
#include <cuda_runtime.h>
#include <cuda_bf16.h>

#define BB    8192
#define BLK   256
#define GRID  592
#define K     64            // time buckets
#define CAP   256           // slots/bucket (mean 128, sigma ~11 -> huge margin)
#define IBLK  512           // i per i-chunk (BLK * IR)
#define NEG_INF __int_as_float(0xff800000)
#define POS_INF __int_as_float(0x7f800000)

__device__ float2 g_jb[K * CAP];     // bucket-scattered all rows {t, r}
__device__ float2 g_eb[K * CAP];     // bucket-scattered event rows {t, 1+r}
__device__ int    g_jcnt[K], g_ecnt[K];
__device__ int    g_jbase[K + 1], g_ebase[K + 1];
__device__ float2 g_jc[BB], g_ec[BB]; // compacted bucket-sorted
__device__ int    g_nev;
__device__ unsigned g_done;
__device__ float  g_ps[GRID];
__device__ float  g_pc[GRID];

__device__ __forceinline__ int bkt(float t) {
    int b = (int)(t * (float)K);
    return min(max(b, 0), K - 1);
}

// ---------- launch 1: bucket scatter ----------
__global__ void k_scatter(const float* __restrict__ risk,
                          const float* __restrict__ tm,
                          const int*   __restrict__ ev) {
    int i = blockIdx.x * BLK + threadIdx.x;
    if (i < BB) {
        float t = tm[i];
        float r = risk[i];
        int   b = bkt(t);
        int   p = atomicAdd(&g_jcnt[b], 1);
        g_jb[b * CAP + p] = make_float2(t, r);
        if (ev[i] == 1) {
            int q = atomicAdd(&g_ecnt[b], 1);
            g_eb[b * CAP + q] = make_float2(t, 1.0f + r);
        }
    }
}

// ---------- launch 2: per-bucket prefix + compact (grid = K blocks) ----------
__global__ void k_compact() {
    const int b   = blockIdx.x;
    const int tid = threadIdx.x;
    __shared__ int jb0, eb0;

    if (tid == 0) {
        int ja = 0, ea = 0;
        for (int x = 0; x < b; x++) { ja += g_jcnt[x]; ea += g_ecnt[x]; }
        jb0 = ja; eb0 = ea;
        if (b == 0) {                 // block 0 additionally publishes bases
            int jj = 0, ee = 0;
            for (int x = 0; x < K; x++) {
                g_jbase[x] = jj; jj += g_jcnt[x];
                g_ebase[x] = ee; ee += g_ecnt[x];
            }
            g_jbase[K] = jj; g_ebase[K] = ee;
            g_nev = ee;
        }
    }
    __syncthreads();

    int jn = g_jcnt[b], en = g_ecnt[b];
    for (int p = tid; p < jn; p += BLK) g_jc[jb0 + p] = g_jb[b * CAP + p];
    for (int p = tid; p < en; p += BLK) g_ec[eb0 + p] = g_eb[b * CAP + p];
}

// ---------- launch 3: tiled pair sweep over (i-chunk, j-bucket) ----------
__global__ void __launch_bounds__(BLK) k_main(float* __restrict__ out) {
    const int tid = threadIdx.x;
    const int nev = g_nev;
    const int nib = (nev + IBLK - 1) / IBLK;
    const int ntiles = nib * K;

    __shared__ float2 sj[CAP];
    float ls0 = 0.f, ls1 = 0.f, lc = 0.f;

    for (int t = blockIdx.x; t < ntiles; t += GRID) {
        const int ic = t % nib;
        const int b  = t / nib;

        const int i0   = ic * IBLK;
        const int iend = min(i0 + IBLK, nev);
        const int bi_lo = bkt(g_ec[i0].x);
        const int bi_hi = bkt(g_ec[iend - 1].x);
        if (bi_lo > b) continue;                 // all pairs invalid

        const int j0 = g_jbase[b];
        const int jn = g_jbase[b + 1] - j0;
        if (jn == 0) continue;

        __syncthreads();
        for (int j = tid; j < jn; j += BLK) sj[j] = g_jc[j0 + j];
        __syncthreads();

        // load 2 i's into registers
        float ti0, ci0, ti1, ci1, fi0 = 0.f, fi1 = 0.f;
        {
            int i = i0 + tid;
            if (i < iend) { float2 e = g_ec[i]; ti0 = e.x; ci0 = e.y; fi0 = (bkt(e.x) == b) ? 1.f : 0.f; }
            else          { ti0 = POS_INF; ci0 = NEG_INF; }
            i += BLK;
            if (i < iend) { float2 e = g_ec[i]; ti1 = e.x; ci1 = e.y; fi1 = (bkt(e.x) == b) ? 1.f : 0.f; }
            else          { ti1 = POS_INF; ci1 = NEG_INF; }
        }

        if (bi_hi < b) {
            // FULL tile: every pair valid, count analytic. 3 instr/pair.
            #pragma unroll 8
            for (int j = 0; j < jn; j++) {
                float rj = sj[j].y;
                ls0 += fmaxf(ci0 - rj, 0.f);
                ls1 += fmaxf(ci1 - rj, 0.f);
            }
        } else {
            // MIXED tile: validity = ti < tj; count only same-bucket pairs
            // (cross-bucket count is analytic).
            #pragma unroll 4
            for (int j = 0; j < jn; j++) {
                float2 p = sj[j];
                bool v0 = ti0 < p.x;
                bool v1 = ti1 < p.x;
                float h0 = fmaxf(ci0 - p.y, 0.f);
                float h1 = fmaxf(ci1 - p.y, 0.f);
                if (v0) { ls0 += h0; lc += fi0; }
                if (v1) { ls1 += h1; lc += fi1; }
            }
        }
    }

    float lsum = ls0 + ls1;

    #pragma unroll
    for (int o = 16; o; o >>= 1) {
        lsum += __shfl_down_sync(0xffffffffu, lsum, o);
        lc   += __shfl_down_sync(0xffffffffu, lc, o);
    }
    __shared__ float ws[BLK / 32], wc[BLK / 32];
    if ((tid & 31) == 0) { ws[tid >> 5] = lsum; wc[tid >> 5] = lc; }
    __syncthreads();
    if (tid == 0) {
        float s = 0.f, c = 0.f;
        #pragma unroll
        for (int k = 0; k < BLK / 32; k++) { s += ws[k]; c += wc[k]; }
        g_ps[blockIdx.x] = s;
        g_pc[blockIdx.x] = c;
    }

    __shared__ int amLast;
    if (tid == 0) {
        __threadfence();
        amLast = (atomicAdd(&g_done, 1u) == GRID - 1);
    }
    __syncthreads();

    if (amLast) {
        __threadfence();
        double s = 0.0, c = 0.0;
        for (int i = tid; i < GRID; i += BLK) {
            s += (double)g_ps[i];
            c += (double)g_pc[i];
        }
        // analytic cross-bucket count: events in bucket b pair with all j above b
        for (int b = tid; b < K; b += BLK)
            c += (double)g_ecnt[b] * (double)(BB - g_jbase[b + 1]);

        #pragma unroll
        for (int o = 16; o; o >>= 1) {
            s += __shfl_down_sync(0xffffffffu, s, o);
            c += __shfl_down_sync(0xffffffffu, c, o);
        }
        __shared__ double fs[BLK / 32], fc[BLK / 32];
        if ((tid & 31) == 0) { fs[tid >> 5] = s; fc[tid >> 5] = c; }
        __syncthreads();
        if (tid == 0) {
            double S = 0.0, C = 0.0;
            #pragma unroll
            for (int k = 0; k < BLK / 32; k++) { S += fs[k]; C += fc[k]; }
            out[0] = (C == 0.0) ? 0.f : (float)(S / C);
        }
        __syncthreads();
        // reset device state for next graph replay
        for (int b = tid; b < K; b += BLK) { g_jcnt[b] = 0; g_ecnt[b] = 0; }
        if (tid == 0) { g_done = 0; g_nev = 0; }
    }
}

extern "C" void kernel_launch(void* const* d_in, const int* in_sizes, int n_in,
                              void* d_out, int out_size) {
    // metadata order: z (unused), risk, time, event
    const float* risk = (const float*)d_in[1];
    const float* tm   = (const float*)d_in[2];
    const int*   ev   = (const int*)d_in[3];
    float*       out  = (float*)d_out;

    k_scatter<<<BB / BLK, BLK>>>(risk, tm, ev);
    k_compact<<<K, BLK>>>();
    k_main<<<GRID, BLK>>>(out);
}